// round 14
// baseline (speedup 1.0000x reference)
#include <cuda_runtime.h>
#include <cuda_bf16.h>
#include <cuda_fp16.h>
#include <math_constants.h>

#define N_S   50000
#define N_P   10000
#define EN    320000
#define D_IN  512
#define D_OUT 256
#define M_PAD 10112   // 79 * 128
#define ROW_SPLIT 8960  // 70 gemm M-tiles overlap; 9-tile exposed tail

// ---------------- scratch (static device globals; no allocation) ----------------
__device__ __align__(16) float g_w1[D_IN];
__device__ __align__(16) float g_w2[D_IN];
__device__ float g_s_src[N_S];
__device__ float g_s_dst[N_P];
__device__ float g_inv[N_P];
__device__ int   g_cnt[N_P];
__device__ int   g_off[N_P + 1];
__device__ int   g_cur[N_P];
__device__ int   g_src_csr[EN];
__device__ float g_alpha[EN];
// fp16 copy of h_s: 51 MB -> L2-resident gather table (written by k_scores)
__device__ __align__(16) __half g_hs16[(size_t)N_S * D_IN];
// aggregated h per dst, bf16 hi/lo split (rows >= N_P stay zero)
__device__ __align__(16) __nv_bfloat16 g_agg_hi[(size_t)M_PAD * D_IN];
__device__ __align__(16) __nv_bfloat16 g_agg_lo[(size_t)M_PAD * D_IN];
// W in bf16 hi/lo split
__device__ __align__(16) __nv_bfloat16 g_W_hi[(size_t)D_OUT * D_IN];
__device__ __align__(16) __nv_bfloat16 g_W_lo[(size_t)D_OUT * D_IN];

__device__ __forceinline__ unsigned short bf_bits(__nv_bfloat16 h) {
    return *reinterpret_cast<unsigned short*>(&h);
}
__device__ __forceinline__ unsigned h2_bits(__half2 h) {
    return *reinterpret_cast<unsigned*>(&h);
}

// ---------------- K0: zero per-dst edge counts ----------------
__global__ void k_zero_cnt() {
    int i = blockIdx.x * blockDim.x + threadIdx.x;
    if (i < N_P) g_cnt[i] = 0;
}

// ---------------- K1: fold attention vector through W ----------------
__global__ void k_fold_w(const float* __restrict__ W, const float* __restrict__ aw) {
    int k = blockIdx.x * 32 + threadIdx.x;   // 16 blocks x 32 threads
    float a1 = 0.f, a2 = 0.f;
    #pragma unroll 8
    for (int d = 0; d < D_OUT; d++) {
        float w = W[d * D_IN + k];
        a1 += w * aw[d];
        a2 += w * aw[D_OUT + d];
    }
    g_w1[k] = a1;
    g_w2[k] = a2;
}

// ---------------- K1b: split W into bf16 hi/lo ----------------
__global__ void k_convw(const float* __restrict__ W) {
    int i = blockIdx.x * blockDim.x + threadIdx.x;
    float v = W[i];
    __nv_bfloat16 hi = __float2bfloat16_rn(v);
    float r = v - __bfloat162float(hi);
    g_W_hi[i] = hi;
    g_W_lo[i] = __float2bfloat16_rn(r);
}

// ---------------- K2: per-node scores + fused fp16 table emission ----------------
// fp32 h_s reads use STREAMING policy (.cs): those lines are dead after this
// kernel and must not evict the g_hs16 table we are writing (which the
// aggregate gather needs L2-resident).
__global__ void k_scores(const float* __restrict__ hs, const float* __restrict__ hp) {
    int gw   = (blockIdx.x * blockDim.x + threadIdx.x) >> 5;
    int lane = threadIdx.x & 31;
    if (gw >= N_S + N_P) return;
    float acc = 0.f;
    if (gw < N_S) {
        const float4* row = (const float4*)(hs + (size_t)gw * D_IN);
        const float4* wv  = (const float4*)g_w1;
        __half* hrow = g_hs16 + (size_t)gw * D_IN;
        #pragma unroll
        for (int i = lane; i < D_IN / 4; i += 32) {
            float4 a = __ldcs(row + i);     // streaming: don't evict hs16
            float4 b = wv[i];
            acc += a.x * b.x + a.y * b.y + a.z * b.z + a.w * b.w;
            uint2 o;
            o.x = h2_bits(__floats2half2_rn(a.x, a.y));
            o.y = h2_bits(__floats2half2_rn(a.z, a.w));
            *reinterpret_cast<uint2*>(hrow + i * 4) = o;   // default: allocate in L2
        }
    } else {
        const float4* row = (const float4*)(hp + (size_t)(gw - N_S) * D_IN);
        const float4* wv  = (const float4*)g_w2;
        #pragma unroll
        for (int i = lane; i < D_IN / 4; i += 32) {
            float4 a = __ldcs(row + i);     // streaming: h_p never reused
            float4 b = wv[i];
            acc += a.x * b.x + a.y * b.y + a.z * b.z + a.w * b.w;
        }
    }
    #pragma unroll
    for (int o = 16; o; o >>= 1) acc += __shfl_xor_sync(0xffffffffu, acc, o);
    if (lane == 0) {
        if (gw < N_S) g_s_src[gw] = acc;
        else          g_s_dst[gw - N_S] = acc;
    }
}

// ---------------- K3: dst histogram (4 edges per thread) ----------------
__global__ void k_count(const int4* __restrict__ dst4) {
    int i = blockIdx.x * blockDim.x + threadIdx.x;
    if (i >= EN / 4) return;
    int4 d = dst4[i];
    atomicAdd(&g_cnt[d.x], 1);
    atomicAdd(&g_cnt[d.y], 1);
    atomicAdd(&g_cnt[d.z], 1);
    atomicAdd(&g_cnt[d.w], 1);
}

// ---------------- K4: exclusive scan of counts -> CSR offsets ----------------
__global__ void k_scan() {
    __shared__ int wsum[32];
    int t    = threadIdx.x;
    int lane = t & 31;
    int wid  = t >> 5;
    int base = t * 10;
    int incl_loc[10];
    int cnts[10];
    int tot = 0;
    if (t < 1000) {
        #pragma unroll
        for (int i = 0; i < 10; i++) {
            int c = g_cnt[base + i];
            cnts[i] = c;
            tot += c;
            incl_loc[i] = tot;
        }
    }
    int incl = tot;
    #pragma unroll
    for (int o = 1; o < 32; o <<= 1) {
        int v = __shfl_up_sync(0xffffffffu, incl, o);
        if (lane >= o) incl += v;
    }
    if (lane == 31) wsum[wid] = incl;
    __syncthreads();
    if (wid == 0) {
        int v = wsum[lane];
        #pragma unroll
        for (int o = 1; o < 32; o <<= 1) {
            int u = __shfl_up_sync(0xffffffffu, v, o);
            if (lane >= o) v += u;
        }
        wsum[lane] = v;
    }
    __syncthreads();
    int warpoff = (wid == 0) ? 0 : wsum[wid - 1];
    int texcl   = warpoff + incl - tot;
    if (t < 1000) {
        #pragma unroll
        for (int i = 0; i < 10; i++) {
            int iv = texcl + incl_loc[i];
            g_off[base + i + 1] = iv;
            g_cur[base + i]     = iv - cnts[i];
        }
    }
    if (t == 0) g_off[0] = 0;
}

// ---------------- K5: scatter src ids into CSR order (4 edges per thread) -------
__global__ void k_scatter(const int4* __restrict__ src4, const int4* __restrict__ dst4) {
    int i = blockIdx.x * blockDim.x + threadIdx.x;
    if (i >= EN / 4) return;
    int4 s = src4[i];
    int4 d = dst4[i];
    int p0 = atomicAdd(&g_cur[d.x], 1); g_src_csr[p0] = s.x;
    int p1 = atomicAdd(&g_cur[d.y], 1); g_src_csr[p1] = s.y;
    int p2 = atomicAdd(&g_cur[d.z], 1); g_src_csr[p2] = s.z;
    int p3 = atomicAdd(&g_cur[d.w], 1); g_src_csr[p3] = s.w;
}

// ---------------- K6: warp-per-dst softmax -> unnormalized ex + g_inv ----------
__global__ void k_softmax() {
    int p    = (blockIdx.x * blockDim.x + threadIdx.x) >> 5;
    int lane = threadIdx.x & 31;
    if (p >= N_P) return;
    int start = g_off[p];
    int cnt   = g_off[p + 1] - start;
    float sd  = g_s_dst[p];

    float m = -CUDART_INF_F;
    for (int j = lane; j < cnt; j += 32) {
        float v = g_s_src[g_src_csr[start + j]] + sd;
        v = (v > 0.f) ? v : 0.01f * v;
        m = fmaxf(m, v);
    }
    #pragma unroll
    for (int o = 16; o; o >>= 1) m = fmaxf(m, __shfl_xor_sync(0xffffffffu, m, o));

    float s = 0.f;
    for (int j = lane; j < cnt; j += 32) {
        float v = g_s_src[g_src_csr[start + j]] + sd;
        v = (v > 0.f) ? v : 0.01f * v;
        float ex = __expf(v - m);
        g_alpha[start + j] = ex;     // unnormalized (max-subtracted)
        s += ex;
    }
    #pragma unroll
    for (int o = 16; o; o >>= 1) s += __shfl_xor_sync(0xffffffffu, s, o);
    if (lane == 0) g_inv[p] = (cnt > 0) ? (1.0f / s) : 0.f;
}

// ---------------- K7: per-dst weighted gather-accumulate (R9-proven shape) ------
// 64 threads/block, block per dst; thread covers 8 cols (uint4 = 8 halves).
__global__ void __launch_bounds__(64) k_aggregate(int pBase) {
    int p = pBase + blockIdx.x;
    int t = threadIdx.x;                       // 0..63
    int start = g_off[p];
    int cnt   = g_off[p + 1] - start;
    float inv = g_inv[p];

    __shared__ int   ss[64];
    __shared__ float ws[64];

    float acc[8] = {0.f, 0.f, 0.f, 0.f, 0.f, 0.f, 0.f, 0.f};
    for (int base = 0; base < cnt; base += 64) {
        int j = base + t;
        if (j < cnt) {
            ss[t] = g_src_csr[start + j];      // coalesced
            ws[t] = g_alpha[start + j];        // coalesced
        }
        __syncthreads();
        int lim = min(64, cnt - base);
        #pragma unroll 8
        for (int q = 0; q < lim; q++) {
            float w = ws[q];
            const uint4* row = (const uint4*)(g_hs16 + (size_t)ss[q] * D_IN) + t;
            uint4 u = __ldg(row);              // 8 halves
            float2 f0 = __half22float2(*reinterpret_cast<__half2*>(&u.x));
            float2 f1 = __half22float2(*reinterpret_cast<__half2*>(&u.y));
            float2 f2 = __half22float2(*reinterpret_cast<__half2*>(&u.z));
            float2 f3 = __half22float2(*reinterpret_cast<__half2*>(&u.w));
            acc[0] += w * f0.x;  acc[1] += w * f0.y;
            acc[2] += w * f1.x;  acc[3] += w * f1.y;
            acc[4] += w * f2.x;  acc[5] += w * f2.y;
            acc[6] += w * f3.x;  acc[7] += w * f3.y;
        }
        __syncthreads();
    }

    // normalize + bf16 hi/lo split for 8 columns, streaming stores
    unsigned hq[4], lq[4];
    #pragma unroll
    for (int i = 0; i < 4; i++) {
        float v0 = acc[2 * i] * inv;
        float v1 = acc[2 * i + 1] * inv;
        __nv_bfloat16 h0 = __float2bfloat16_rn(v0);
        __nv_bfloat16 h1 = __float2bfloat16_rn(v1);
        unsigned short l0 = bf_bits(__float2bfloat16_rn(v0 - __bfloat162float(h0)));
        unsigned short l1 = bf_bits(__float2bfloat16_rn(v1 - __bfloat162float(h1)));
        hq[i] = (unsigned)bf_bits(h0) | ((unsigned)bf_bits(h1) << 16);
        lq[i] = (unsigned)l0 | ((unsigned)l1 << 16);
    }
    size_t obase = (size_t)p * D_IN + t * 8;
    asm volatile("st.global.cs.v4.u32 [%0], {%1,%2,%3,%4};"
                 :: "l"(g_agg_hi + obase), "r"(hq[0]), "r"(hq[1]), "r"(hq[2]), "r"(hq[3]));
    asm volatile("st.global.cs.v4.u32 [%0], {%1,%2,%3,%4};"
                 :: "l"(g_agg_lo + obase), "r"(lq[0]), "r"(lq[1]), "r"(lq[2]), "r"(lq[3]));
}

// ---------------- K8: out = agg @ W^T via bf16-split MMA + ldmatrix -------------
#define SMS 24   // smem row stride in bf16 (48B: 16B-aligned, conflict-free)

__device__ __forceinline__ void mma_bf16(float d[4],
                                         unsigned a0, unsigned a1, unsigned a2, unsigned a3,
                                         unsigned b0, unsigned b1) {
    asm volatile(
        "mma.sync.aligned.m16n8k16.row.col.f32.bf16.bf16.f32 "
        "{%0,%1,%2,%3}, {%4,%5,%6,%7}, {%8,%9}, {%0,%1,%2,%3};\n"
        : "+f"(d[0]), "+f"(d[1]), "+f"(d[2]), "+f"(d[3])
        : "r"(a0), "r"(a1), "r"(a2), "r"(a3), "r"(b0), "r"(b1));
}

__device__ __forceinline__ void ldsm4(unsigned& r0, unsigned& r1, unsigned& r2, unsigned& r3,
                                      unsigned addr) {
    asm volatile("ldmatrix.sync.aligned.m8n8.x4.shared.b16 {%0,%1,%2,%3}, [%4];"
                 : "=r"(r0), "=r"(r1), "=r"(r2), "=r"(r3) : "r"(addr));
}

__global__ void __launch_bounds__(256) k_gemm_mma(float* __restrict__ out, int bmBase) {
    __shared__ __align__(16) __nv_bfloat16 sAh[128 * SMS];
    __shared__ __align__(16) __nv_bfloat16 sAl[128 * SMS];
    __shared__ __align__(16) __nv_bfloat16 sBh[128 * SMS];
    __shared__ __align__(16) __nv_bfloat16 sBl[128 * SMS];

    const int bm = (blockIdx.x + bmBase) * 128;
    const int bn = blockIdx.y * 128;
    const int tid  = threadIdx.x;
    const int lane = tid & 31;
    const int warp = tid >> 5;
    const int wm = (warp >> 1) * 32;
    const int wn = (warp & 1) * 64;
    const int g  = lane >> 2;
    const int tg = lane & 3;

    const int lrow = tid >> 1;
    const int lc8  = (tid & 1) * 8;

    const __nv_bfloat16* gAh = g_agg_hi + (size_t)(bm + lrow) * D_IN + lc8;
    const __nv_bfloat16* gAl = g_agg_lo + (size_t)(bm + lrow) * D_IN + lc8;
    const __nv_bfloat16* gBh = g_W_hi   + (size_t)(bn + lrow) * D_IN + lc8;
    const __nv_bfloat16* gBl = g_W_lo   + (size_t)(bn + lrow) * D_IN + lc8;

    float d[2][8][4];
    #pragma unroll
    for (int mt = 0; mt < 2; mt++)
        #pragma unroll
        for (int nt = 0; nt < 8; nt++)
            #pragma unroll
            for (int i = 0; i < 4; i++) d[mt][nt][i] = 0.f;

    uint4 rah = *(const uint4*)gAh;
    uint4 ral = *(const uint4*)gAl;
    uint4 rbh = *(const uint4*)gBh;
    uint4 rbl = *(const uint4*)gBl;

    const int sidx = lrow * SMS + lc8;

    const unsigned baseAh = (unsigned)__cvta_generic_to_shared(sAh);
    const unsigned baseAl = (unsigned)__cvta_generic_to_shared(sAl);
    const unsigned baseBh = (unsigned)__cvta_generic_to_shared(sBh);
    const unsigned baseBl = (unsigned)__cvta_generic_to_shared(sBl);

    const int arow = (lane & 15);
    const int akb  = (lane >> 4) * 16;
    unsigned aAddr[2], aAddrL[2];
    #pragma unroll
    for (int mt = 0; mt < 2; mt++) {
        int r = wm + mt * 16 + arow;
        aAddr[mt]  = baseAh + r * (SMS * 2) + akb;
        aAddrL[mt] = baseAl + r * (SMS * 2) + akb;
    }
    const int brow = (lane & 7) + ((lane >> 4) & 1) * 8;
    const int bkb  = ((lane >> 3) & 1) * 16;
    unsigned bAddr[4], bAddrL[4];
    #pragma unroll
    for (int ntp = 0; ntp < 4; ntp++) {
        int r = wn + ntp * 16 + brow;
        bAddr[ntp]  = baseBh + r * (SMS * 2) + bkb;
        bAddrL[ntp] = baseBl + r * (SMS * 2) + bkb;
    }

    for (int ks = 0; ks < D_IN / 16; ks++) {
        *(uint4*)(sAh + sidx) = rah;
        *(uint4*)(sAl + sidx) = ral;
        *(uint4*)(sBh + sidx) = rbh;
        *(uint4*)(sBl + sidx) = rbl;
        __syncthreads();

        if (ks < D_IN / 16 - 1) {
            int koff = (ks + 1) * 16;
            rah = *(const uint4*)(gAh + koff);
            ral = *(const uint4*)(gAl + koff);
            rbh = *(const uint4*)(gBh + koff);
            rbl = *(const uint4*)(gBl + koff);
        }

        unsigned ah[2][4], al[2][4];
        #pragma unroll
        for (int mt = 0; mt < 2; mt++) {
            ldsm4(ah[mt][0], ah[mt][1], ah[mt][2], ah[mt][3], aAddr[mt]);
            ldsm4(al[mt][0], al[mt][1], al[mt][2], al[mt][3], aAddrL[mt]);
        }
        unsigned bh[4][4], bl[4][4];
        #pragma unroll
        for (int ntp = 0; ntp < 4; ntp++) {
            ldsm4(bh[ntp][0], bh[ntp][1], bh[ntp][2], bh[ntp][3], bAddr[ntp]);
            ldsm4(bl[ntp][0], bl[ntp][1], bl[ntp][2], bl[ntp][3], bAddrL[ntp]);
        }

        #pragma unroll
        for (int nt = 0; nt < 8; nt++) {
            int ntp = nt >> 1;
            int o   = (nt & 1) * 2;
            unsigned bh0 = bh[ntp][o], bh1 = bh[ntp][o + 1];
            unsigned bl0 = bl[ntp][o], bl1 = bl[ntp][o + 1];
            #pragma unroll
            for (int mt = 0; mt < 2; mt++) {
                mma_bf16(d[mt][nt], ah[mt][0], ah[mt][1], ah[mt][2], ah[mt][3], bh0, bh1);
                mma_bf16(d[mt][nt], ah[mt][0], ah[mt][1], ah[mt][2], ah[mt][3], bl0, bl1);
                mma_bf16(d[mt][nt], al[mt][0], al[mt][1], al[mt][2], al[mt][3], bh0, bh1);
            }
        }
        __syncthreads();
    }

    #pragma unroll
    for (int mt = 0; mt < 2; mt++) {
        #pragma unroll
        for (int nt = 0; nt < 8; nt++) {
            int r0 = bm + wm + mt * 16 + g;
            int c  = bn + wn + nt * 8 + tg * 2;
            if (r0 < N_P) {
                float2 v0 = make_float2(d[mt][nt][0], d[mt][nt][1]);
                *(float2*)(out + (size_t)r0 * D_OUT + c) = v0;
            }
            if (r0 + 8 < N_P) {
                float2 v1 = make_float2(d[mt][nt][2], d[mt][nt][3]);
                *(float2*)(out + (size_t)(r0 + 8) * D_OUT + c) = v1;
            }
        }
    }
}

// ---------------- stream/event context (created at load, before harness checkpoints)
struct HxCtx {
    cudaStream_t sB, sC;
    cudaEvent_t evRoot, evB, evG1, evG2, evC;
    HxCtx() {
        cudaStreamCreateWithFlags(&sB, cudaStreamNonBlocking);
        cudaStreamCreateWithFlags(&sC, cudaStreamNonBlocking);
        cudaEventCreateWithFlags(&evRoot, cudaEventDisableTiming);
        cudaEventCreateWithFlags(&evB,    cudaEventDisableTiming);
        cudaEventCreateWithFlags(&evG1,   cudaEventDisableTiming);
        cudaEventCreateWithFlags(&evG2,   cudaEventDisableTiming);
        cudaEventCreateWithFlags(&evC,    cudaEventDisableTiming);
    }
};
static HxCtx hx;

// ---------------- launch ----------------
extern "C" void kernel_launch(void* const* d_in, const int* in_sizes, int n_in,
                              void* d_out, int out_size) {
    const float* hs  = (const float*)d_in[0];
    const float* hp  = (const float*)d_in[1];
    const float* W   = (const float*)d_in[2];
    const float* aw  = (const float*)d_in[3];
    const int*   src = (const int*)d_in[4];
    const int*   dst = (const int*)d_in[5];
    float*       out = (float*)d_out;

    // fork
    cudaEventRecord(hx.evRoot, 0);
    cudaStreamWaitEvent(hx.sB, hx.evRoot, 0);
    cudaStreamWaitEvent(hx.sC, hx.evRoot, 0);

    // chain B (edge structure): zero -> count -> scan -> scatter
    k_zero_cnt<<<(N_P + 255) / 256, 256, 0, hx.sB>>>();
    k_count<<<(EN / 4 + 255) / 256, 256, 0, hx.sB>>>((const int4*)dst);
    k_scan<<<1, 1024, 0, hx.sB>>>();
    k_scatter<<<(EN / 4 + 255) / 256, 256, 0, hx.sB>>>((const int4*)src, (const int4*)dst);
    cudaEventRecord(hx.evB, hx.sB);

    // chain C (weights): convw, later gemm
    k_convw<<<(D_OUT * D_IN) / 1024, 1024, 0, hx.sC>>>(W);

    // chain 0: fold -> scores(+fp16 table) -> join B -> softmax -> aggregate chunks
    k_fold_w<<<16, 32>>>(W, aw);
    k_scores<<<((N_S + N_P) * 32 + 255) / 256, 256>>>(hs, hp);
    cudaStreamWaitEvent(0, hx.evB, 0);
    k_softmax<<<(N_P * 32 + 255) / 256, 256>>>();
    k_aggregate<<<ROW_SPLIT, 64>>>(0);
    cudaEventRecord(hx.evG1, 0);
    k_aggregate<<<N_P - ROW_SPLIT, 64>>>(ROW_SPLIT);
    cudaEventRecord(hx.evG2, 0);

    // gemm pipelined on chain C (bulk overlaps the small second aggregate chunk)
    cudaStreamWaitEvent(hx.sC, hx.evG1, 0);
    k_gemm_mma<<<dim3(ROW_SPLIT / 128, D_OUT / 128), 256, 0, hx.sC>>>(out, 0);
    cudaStreamWaitEvent(hx.sC, hx.evG2, 0);
    k_gemm_mma<<<dim3(M_PAD / 128 - ROW_SPLIT / 128, D_OUT / 128), 256, 0, hx.sC>>>(out, ROW_SPLIT / 128);
    cudaEventRecord(hx.evC, hx.sC);

    // join everything back to the capture stream
    cudaStreamWaitEvent(0, hx.evC, 0);
}

// round 15
// speedup vs baseline: 1.0561x; 1.0561x over previous
#include <cuda_runtime.h>
#include <cuda_bf16.h>
#include <cuda_fp16.h>
#include <math_constants.h>

#define N_S   50000
#define N_P   10000
#define EN    320000
#define D_IN  512
#define D_OUT 256
#define M_PAD 10112   // 79 * 128
#define ROW_SPLIT 5120  // 40 gemm M-tiles

// ---------------- scratch (static device globals; no allocation) ----------------
__device__ __align__(16) float g_w1[D_IN];
__device__ __align__(16) float g_w2[D_IN];
__device__ __align__(16) float g_w1p[8][D_IN];
__device__ __align__(16) float g_w2p[8][D_IN];
__device__ float g_s_src[N_S];
__device__ float g_s_dst[N_P];
__device__ float g_inv[N_P];
__device__ int   g_cnt[N_P];
__device__ int   g_off[N_P + 1];
__device__ int   g_cur[N_P];
__device__ int   g_src_csr[EN];
__device__ float g_alpha[EN];
// fp16 copy of h_s: 51 MB gather table (written by k_scores, fused)
__device__ __align__(16) __half g_hs16[(size_t)N_S * D_IN];
// aggregated h per dst, bf16 hi/lo split (rows >= N_P stay zero)
__device__ __align__(16) __nv_bfloat16 g_agg_hi[(size_t)M_PAD * D_IN];
__device__ __align__(16) __nv_bfloat16 g_agg_lo[(size_t)M_PAD * D_IN];
// W in bf16 hi/lo split
__device__ __align__(16) __nv_bfloat16 g_W_hi[(size_t)D_OUT * D_IN];
__device__ __align__(16) __nv_bfloat16 g_W_lo[(size_t)D_OUT * D_IN];

__device__ __forceinline__ unsigned short bf_bits(__nv_bfloat16 h) {
    return *reinterpret_cast<unsigned short*>(&h);
}
__device__ __forceinline__ unsigned h2_bits(__half2 h) {
    return *reinterpret_cast<unsigned*>(&h);
}

// ---------------- K0: zero per-dst edge counts ----------------
__global__ void k_zero_cnt() {
    int i = blockIdx.x * blockDim.x + threadIdx.x;
    if (i < N_P) g_cnt[i] = 0;
}

// ---------------- K1a: fold attention vector, phase 1 (partials) ----------------
// 64 blocks x 64 threads: block = (kb = bx&7 -> k-slice of 64, db = bx>>3 -> d-slice of 32)
__global__ void __launch_bounds__(64) k_fold_part(const float* __restrict__ W,
                                                  const float* __restrict__ aw) {
    int kb = blockIdx.x & 7;
    int db = blockIdx.x >> 3;
    int k  = kb * 64 + threadIdx.x;
    int d0 = db * 32;
    float a1 = 0.f, a2 = 0.f;
    #pragma unroll
    for (int i = 0; i < 32; i++) {
        int d = d0 + i;
        float w = __ldg(&W[d * D_IN + k]);   // coalesced across the 64 threads
        a1 += w * __ldg(&aw[d]);
        a2 += w * __ldg(&aw[D_OUT + d]);
    }
    g_w1p[db][k] = a1;
    g_w2p[db][k] = a2;
}

// ---------------- K1a': fold phase 2 (reduce 8 partials) ----------------
__global__ void k_fold_red() {
    int k = threadIdx.x;   // 512 threads
    float a1 = 0.f, a2 = 0.f;
    #pragma unroll
    for (int i = 0; i < 8; i++) {
        a1 += g_w1p[i][k];
        a2 += g_w2p[i][k];
    }
    g_w1[k] = a1;
    g_w2[k] = a2;
}

// ---------------- K1b: split W into bf16 hi/lo ----------------
__global__ void k_convw(const float* __restrict__ W) {
    int i = blockIdx.x * blockDim.x + threadIdx.x;
    float v = W[i];
    __nv_bfloat16 hi = __float2bfloat16_rn(v);
    float r = v - __bfloat162float(hi);
    g_W_hi[i] = hi;
    g_W_lo[i] = __float2bfloat16_rn(r);
}

// ---------------- K2: per-node scores + fused fp16 table emission ----------------
__global__ void k_scores(const float* __restrict__ hs, const float* __restrict__ hp) {
    int gw   = (blockIdx.x * blockDim.x + threadIdx.x) >> 5;
    int lane = threadIdx.x & 31;
    if (gw >= N_S + N_P) return;
    float acc = 0.f;
    if (gw < N_S) {
        const float4* row = (const float4*)(hs + (size_t)gw * D_IN);
        const float4* wv  = (const float4*)g_w1;
        __half* hrow = g_hs16 + (size_t)gw * D_IN;
        #pragma unroll
        for (int i = lane; i < D_IN / 4; i += 32) {
            float4 a = __ldg(row + i);
            float4 b = wv[i];
            acc += a.x * b.x + a.y * b.y + a.z * b.z + a.w * b.w;
            uint2 o;
            o.x = h2_bits(__floats2half2_rn(a.x, a.y));
            o.y = h2_bits(__floats2half2_rn(a.z, a.w));
            *reinterpret_cast<uint2*>(hrow + i * 4) = o;
        }
    } else {
        const float4* row = (const float4*)(hp + (size_t)(gw - N_S) * D_IN);
        const float4* wv  = (const float4*)g_w2;
        #pragma unroll
        for (int i = lane; i < D_IN / 4; i += 32) {
            float4 a = __ldcs(row + i);     // streaming: h_p never reused
            float4 b = wv[i];
            acc += a.x * b.x + a.y * b.y + a.z * b.z + a.w * b.w;
        }
    }
    #pragma unroll
    for (int o = 16; o; o >>= 1) acc += __shfl_xor_sync(0xffffffffu, acc, o);
    if (lane == 0) {
        if (gw < N_S) g_s_src[gw] = acc;
        else          g_s_dst[gw - N_S] = acc;
    }
}

// ---------------- K3: dst histogram (4 edges per thread) ----------------
__global__ void k_count(const int4* __restrict__ dst4) {
    int i = blockIdx.x * blockDim.x + threadIdx.x;
    if (i >= EN / 4) return;
    int4 d = dst4[i];
    atomicAdd(&g_cnt[d.x], 1);
    atomicAdd(&g_cnt[d.y], 1);
    atomicAdd(&g_cnt[d.z], 1);
    atomicAdd(&g_cnt[d.w], 1);
}

// ---------------- K4: exclusive scan of counts -> CSR offsets ----------------
__global__ void k_scan() {
    __shared__ int wsum[32];
    int t    = threadIdx.x;
    int lane = t & 31;
    int wid  = t >> 5;
    int base = t * 10;
    int incl_loc[10];
    int cnts[10];
    int tot = 0;
    if (t < 1000) {
        #pragma unroll
        for (int i = 0; i < 10; i++) {
            int c = g_cnt[base + i];
            cnts[i] = c;
            tot += c;
            incl_loc[i] = tot;
        }
    }
    int incl = tot;
    #pragma unroll
    for (int o = 1; o < 32; o <<= 1) {
        int v = __shfl_up_sync(0xffffffffu, incl, o);
        if (lane >= o) incl += v;
    }
    if (lane == 31) wsum[wid] = incl;
    __syncthreads();
    if (wid == 0) {
        int v = wsum[lane];
        #pragma unroll
        for (int o = 1; o < 32; o <<= 1) {
            int u = __shfl_up_sync(0xffffffffu, v, o);
            if (lane >= o) v += u;
        }
        wsum[lane] = v;
    }
    __syncthreads();
    int warpoff = (wid == 0) ? 0 : wsum[wid - 1];
    int texcl   = warpoff + incl - tot;
    if (t < 1000) {
        #pragma unroll
        for (int i = 0; i < 10; i++) {
            int iv = texcl + incl_loc[i];
            g_off[base + i + 1] = iv;
            g_cur[base + i]     = iv - cnts[i];
        }
    }
    if (t == 0) g_off[0] = 0;
}

// ---------------- K5: scatter src ids into CSR order (4 edges per thread) -------
__global__ void k_scatter(const int4* __restrict__ src4, const int4* __restrict__ dst4) {
    int i = blockIdx.x * blockDim.x + threadIdx.x;
    if (i >= EN / 4) return;
    int4 s = src4[i];
    int4 d = dst4[i];
    int p0 = atomicAdd(&g_cur[d.x], 1); g_src_csr[p0] = s.x;
    int p1 = atomicAdd(&g_cur[d.y], 1); g_src_csr[p1] = s.y;
    int p2 = atomicAdd(&g_cur[d.z], 1); g_src_csr[p2] = s.z;
    int p3 = atomicAdd(&g_cur[d.w], 1); g_src_csr[p3] = s.w;
}

// ---------------- K6: warp-per-dst softmax -> unnormalized ex + g_inv ----------
__global__ void k_softmax() {
    int p    = (blockIdx.x * blockDim.x + threadIdx.x) >> 5;
    int lane = threadIdx.x & 31;
    if (p >= N_P) return;
    int start = g_off[p];
    int cnt   = g_off[p + 1] - start;
    float sd  = g_s_dst[p];

    float m = -CUDART_INF_F;
    for (int j = lane; j < cnt; j += 32) {
        float v = g_s_src[g_src_csr[start + j]] + sd;
        v = (v > 0.f) ? v : 0.01f * v;
        m = fmaxf(m, v);
    }
    #pragma unroll
    for (int o = 16; o; o >>= 1) m = fmaxf(m, __shfl_xor_sync(0xffffffffu, m, o));

    float s = 0.f;
    for (int j = lane; j < cnt; j += 32) {
        float v = g_s_src[g_src_csr[start + j]] + sd;
        v = (v > 0.f) ? v : 0.01f * v;
        float ex = __expf(v - m);
        g_alpha[start + j] = ex;     // unnormalized (max-subtracted)
        s += ex;
    }
    #pragma unroll
    for (int o = 16; o; o >>= 1) s += __shfl_xor_sync(0xffffffffu, s, o);
    if (lane == 0) g_inv[p] = (cnt > 0) ? (1.0f / s) : 0.f;
}

// ---------------- K7: per-dst weighted gather-accumulate (R9-proven shape) ------
// 64 threads/block, block per dst; thread covers 8 cols (uint4 = 8 halves).
__global__ void __launch_bounds__(64) k_aggregate(int pBase) {
    int p = pBase + blockIdx.x;
    int t = threadIdx.x;                       // 0..63
    int start = g_off[p];
    int cnt   = g_off[p + 1] - start;
    float inv = g_inv[p];

    __shared__ int   ss[64];
    __shared__ float ws[64];

    float acc[8] = {0.f, 0.f, 0.f, 0.f, 0.f, 0.f, 0.f, 0.f};
    for (int base = 0; base < cnt; base += 64) {
        int j = base + t;
        if (j < cnt) {
            ss[t] = g_src_csr[start + j];      // coalesced
            ws[t] = g_alpha[start + j];        // coalesced
        }
        __syncthreads();
        int lim = min(64, cnt - base);
        #pragma unroll 8
        for (int q = 0; q < lim; q++) {
            float w = ws[q];
            const uint4* row = (const uint4*)(g_hs16 + (size_t)ss[q] * D_IN) + t;
            uint4 u = __ldg(row);              // 8 halves
            float2 f0 = __half22float2(*reinterpret_cast<__half2*>(&u.x));
            float2 f1 = __half22float2(*reinterpret_cast<__half2*>(&u.y));
            float2 f2 = __half22float2(*reinterpret_cast<__half2*>(&u.z));
            float2 f3 = __half22float2(*reinterpret_cast<__half2*>(&u.w));
            acc[0] += w * f0.x;  acc[1] += w * f0.y;
            acc[2] += w * f1.x;  acc[3] += w * f1.y;
            acc[4] += w * f2.x;  acc[5] += w * f2.y;
            acc[6] += w * f3.x;  acc[7] += w * f3.y;
        }
        __syncthreads();
    }

    // normalize + bf16 hi/lo split for 8 columns, streaming stores
    unsigned hq[4], lq[4];
    #pragma unroll
    for (int i = 0; i < 4; i++) {
        float v0 = acc[2 * i] * inv;
        float v1 = acc[2 * i + 1] * inv;
        __nv_bfloat16 h0 = __float2bfloat16_rn(v0);
        __nv_bfloat16 h1 = __float2bfloat16_rn(v1);
        unsigned short l0 = bf_bits(__float2bfloat16_rn(v0 - __bfloat162float(h0)));
        unsigned short l1 = bf_bits(__float2bfloat16_rn(v1 - __bfloat162float(h1)));
        hq[i] = (unsigned)bf_bits(h0) | ((unsigned)bf_bits(h1) << 16);
        lq[i] = (unsigned)l0 | ((unsigned)l1 << 16);
    }
    size_t obase = (size_t)p * D_IN + t * 8;
    asm volatile("st.global.cs.v4.u32 [%0], {%1,%2,%3,%4};"
                 :: "l"(g_agg_hi + obase), "r"(hq[0]), "r"(hq[1]), "r"(hq[2]), "r"(hq[3]));
    asm volatile("st.global.cs.v4.u32 [%0], {%1,%2,%3,%4};"
                 :: "l"(g_agg_lo + obase), "r"(lq[0]), "r"(lq[1]), "r"(lq[2]), "r"(lq[3]));
}

// ---------------- K8: out = agg @ W^T via bf16-split MMA + ldmatrix -------------
#define SMS 24   // smem row stride in bf16 (48B: 16B-aligned, conflict-free)

__device__ __forceinline__ void mma_bf16(float d[4],
                                         unsigned a0, unsigned a1, unsigned a2, unsigned a3,
                                         unsigned b0, unsigned b1) {
    asm volatile(
        "mma.sync.aligned.m16n8k16.row.col.f32.bf16.bf16.f32 "
        "{%0,%1,%2,%3}, {%4,%5,%6,%7}, {%8,%9}, {%0,%1,%2,%3};\n"
        : "+f"(d[0]), "+f"(d[1]), "+f"(d[2]), "+f"(d[3])
        : "r"(a0), "r"(a1), "r"(a2), "r"(a3), "r"(b0), "r"(b1));
}

__device__ __forceinline__ void ldsm4(unsigned& r0, unsigned& r1, unsigned& r2, unsigned& r3,
                                      unsigned addr) {
    asm volatile("ldmatrix.sync.aligned.m8n8.x4.shared.b16 {%0,%1,%2,%3}, [%4];"
                 : "=r"(r0), "=r"(r1), "=r"(r2), "=r"(r3) : "r"(addr));
}

__global__ void __launch_bounds__(256) k_gemm_mma(float* __restrict__ out, int bmBase) {
    __shared__ __align__(16) __nv_bfloat16 sAh[128 * SMS];
    __shared__ __align__(16) __nv_bfloat16 sAl[128 * SMS];
    __shared__ __align__(16) __nv_bfloat16 sBh[128 * SMS];
    __shared__ __align__(16) __nv_bfloat16 sBl[128 * SMS];

    const int bm = (blockIdx.x + bmBase) * 128;
    const int bn = blockIdx.y * 128;
    const int tid  = threadIdx.x;
    const int lane = tid & 31;
    const int warp = tid >> 5;
    const int wm = (warp >> 1) * 32;
    const int wn = (warp & 1) * 64;
    const int g  = lane >> 2;
    const int tg = lane & 3;

    const int lrow = tid >> 1;
    const int lc8  = (tid & 1) * 8;

    const __nv_bfloat16* gAh = g_agg_hi + (size_t)(bm + lrow) * D_IN + lc8;
    const __nv_bfloat16* gAl = g_agg_lo + (size_t)(bm + lrow) * D_IN + lc8;
    const __nv_bfloat16* gBh = g_W_hi   + (size_t)(bn + lrow) * D_IN + lc8;
    const __nv_bfloat16* gBl = g_W_lo   + (size_t)(bn + lrow) * D_IN + lc8;

    float d[2][8][4];
    #pragma unroll
    for (int mt = 0; mt < 2; mt++)
        #pragma unroll
        for (int nt = 0; nt < 8; nt++)
            #pragma unroll
            for (int i = 0; i < 4; i++) d[mt][nt][i] = 0.f;

    uint4 rah = *(const uint4*)gAh;
    uint4 ral = *(const uint4*)gAl;
    uint4 rbh = *(const uint4*)gBh;
    uint4 rbl = *(const uint4*)gBl;

    const int sidx = lrow * SMS + lc8;

    const unsigned baseAh = (unsigned)__cvta_generic_to_shared(sAh);
    const unsigned baseAl = (unsigned)__cvta_generic_to_shared(sAl);
    const unsigned baseBh = (unsigned)__cvta_generic_to_shared(sBh);
    const unsigned baseBl = (unsigned)__cvta_generic_to_shared(sBl);

    const int arow = (lane & 15);
    const int akb  = (lane >> 4) * 16;
    unsigned aAddr[2], aAddrL[2];
    #pragma unroll
    for (int mt = 0; mt < 2; mt++) {
        int r = wm + mt * 16 + arow;
        aAddr[mt]  = baseAh + r * (SMS * 2) + akb;
        aAddrL[mt] = baseAl + r * (SMS * 2) + akb;
    }
    const int brow = (lane & 7) + ((lane >> 4) & 1) * 8;
    const int bkb  = ((lane >> 3) & 1) * 16;
    unsigned bAddr[4], bAddrL[4];
    #pragma unroll
    for (int ntp = 0; ntp < 4; ntp++) {
        int r = wn + ntp * 16 + brow;
        bAddr[ntp]  = baseBh + r * (SMS * 2) + bkb;
        bAddrL[ntp] = baseBl + r * (SMS * 2) + bkb;
    }

    for (int ks = 0; ks < D_IN / 16; ks++) {
        *(uint4*)(sAh + sidx) = rah;
        *(uint4*)(sAl + sidx) = ral;
        *(uint4*)(sBh + sidx) = rbh;
        *(uint4*)(sBl + sidx) = rbl;
        __syncthreads();

        if (ks < D_IN / 16 - 1) {
            int koff = (ks + 1) * 16;
            rah = *(const uint4*)(gAh + koff);
            ral = *(const uint4*)(gAl + koff);
            rbh = *(const uint4*)(gBh + koff);
            rbl = *(const uint4*)(gBl + koff);
        }

        unsigned ah[2][4], al[2][4];
        #pragma unroll
        for (int mt = 0; mt < 2; mt++) {
            ldsm4(ah[mt][0], ah[mt][1], ah[mt][2], ah[mt][3], aAddr[mt]);
            ldsm4(al[mt][0], al[mt][1], al[mt][2], al[mt][3], aAddrL[mt]);
        }
        unsigned bh[4][4], bl[4][4];
        #pragma unroll
        for (int ntp = 0; ntp < 4; ntp++) {
            ldsm4(bh[ntp][0], bh[ntp][1], bh[ntp][2], bh[ntp][3], bAddr[ntp]);
            ldsm4(bl[ntp][0], bl[ntp][1], bl[ntp][2], bl[ntp][3], bAddrL[ntp]);
        }

        #pragma unroll
        for (int nt = 0; nt < 8; nt++) {
            int ntp = nt >> 1;
            int o   = (nt & 1) * 2;
            unsigned bh0 = bh[ntp][o], bh1 = bh[ntp][o + 1];
            unsigned bl0 = bl[ntp][o], bl1 = bl[ntp][o + 1];
            #pragma unroll
            for (int mt = 0; mt < 2; mt++) {
                mma_bf16(d[mt][nt], ah[mt][0], ah[mt][1], ah[mt][2], ah[mt][3], bh0, bh1);
                mma_bf16(d[mt][nt], ah[mt][0], ah[mt][1], ah[mt][2], ah[mt][3], bl0, bl1);
                mma_bf16(d[mt][nt], al[mt][0], al[mt][1], al[mt][2], al[mt][3], bh0, bh1);
            }
        }
        __syncthreads();
    }

    #pragma unroll
    for (int mt = 0; mt < 2; mt++) {
        #pragma unroll
        for (int nt = 0; nt < 8; nt++) {
            int r0 = bm + wm + mt * 16 + g;
            int c  = bn + wn + nt * 8 + tg * 2;
            if (r0 < N_P) {
                float2 v0 = make_float2(d[mt][nt][0], d[mt][nt][1]);
                *(float2*)(out + (size_t)r0 * D_OUT + c) = v0;
            }
            if (r0 + 8 < N_P) {
                float2 v1 = make_float2(d[mt][nt][2], d[mt][nt][3]);
                *(float2*)(out + (size_t)(r0 + 8) * D_OUT + c) = v1;
            }
        }
    }
}

// ---------------- stream/event context (created at load, before harness checkpoints)
struct HxCtx {
    cudaStream_t sB, sC;
    cudaEvent_t evRoot, evB, evG1, evG2, evC;
    HxCtx() {
        cudaStreamCreateWithFlags(&sB, cudaStreamNonBlocking);
        cudaStreamCreateWithFlags(&sC, cudaStreamNonBlocking);
        cudaEventCreateWithFlags(&evRoot, cudaEventDisableTiming);
        cudaEventCreateWithFlags(&evB,    cudaEventDisableTiming);
        cudaEventCreateWithFlags(&evG1,   cudaEventDisableTiming);
        cudaEventCreateWithFlags(&evG2,   cudaEventDisableTiming);
        cudaEventCreateWithFlags(&evC,    cudaEventDisableTiming);
    }
};
static HxCtx hx;

// ---------------- launch ----------------
extern "C" void kernel_launch(void* const* d_in, const int* in_sizes, int n_in,
                              void* d_out, int out_size) {
    const float* hs  = (const float*)d_in[0];
    const float* hp  = (const float*)d_in[1];
    const float* W   = (const float*)d_in[2];
    const float* aw  = (const float*)d_in[3];
    const int*   src = (const int*)d_in[4];
    const int*   dst = (const int*)d_in[5];
    float*       out = (float*)d_out;

    // fork
    cudaEventRecord(hx.evRoot, 0);
    cudaStreamWaitEvent(hx.sB, hx.evRoot, 0);
    cudaStreamWaitEvent(hx.sC, hx.evRoot, 0);

    // chain B (edge structure): zero -> count -> scan -> scatter
    k_zero_cnt<<<(N_P + 255) / 256, 256, 0, hx.sB>>>();
    k_count<<<(EN / 4 + 255) / 256, 256, 0, hx.sB>>>((const int4*)dst);
    k_scan<<<1, 1024, 0, hx.sB>>>();
    k_scatter<<<(EN / 4 + 255) / 256, 256, 0, hx.sB>>>((const int4*)src, (const int4*)dst);
    cudaEventRecord(hx.evB, hx.sB);

    // chain C (weights): convw, later gemm
    k_convw<<<(D_OUT * D_IN) / 1024, 1024, 0, hx.sC>>>(W);

    // chain 0: fold (2-phase) -> scores(+fp16 table) -> join B -> softmax -> aggregate
    k_fold_part<<<64, 64>>>(W, aw);
    k_fold_red<<<1, 512>>>();
    k_scores<<<((N_S + N_P) * 32 + 255) / 256, 256>>>(hs, hp);
    cudaStreamWaitEvent(0, hx.evB, 0);
    k_softmax<<<(N_P * 32 + 255) / 256, 256>>>();
    k_aggregate<<<ROW_SPLIT, 64>>>(0);
    cudaEventRecord(hx.evG1, 0);
    k_aggregate<<<N_P - ROW_SPLIT, 64>>>(ROW_SPLIT);
    cudaEventRecord(hx.evG2, 0);

    // gemm pipelined on chain C (overlaps second aggregate half)
    cudaStreamWaitEvent(hx.sC, hx.evG1, 0);
    k_gemm_mma<<<dim3(ROW_SPLIT / 128, D_OUT / 128), 256, 0, hx.sC>>>(out, 0);
    cudaStreamWaitEvent(hx.sC, hx.evG2, 0);
    k_gemm_mma<<<dim3(M_PAD / 128 - ROW_SPLIT / 128, D_OUT / 128), 256, 0, hx.sC>>>(out, ROW_SPLIT / 128);
    cudaEventRecord(hx.evC, hx.sC);

    // join everything back to the capture stream
    cudaStreamWaitEvent(0, hx.evC, 0);
}

// round 16
// speedup vs baseline: 1.2495x; 1.1831x over previous
#include <cuda_runtime.h>
#include <cuda_fp16.h>
#include <math_constants.h>

#define N_S   50000
#define N_P   10000
#define EN    320000
#define D_IN  512
#define D_OUT 256
#define M_PAD 10112   // 79 * 128
#define ROW_SPLIT 5120  // 40 gemm M-tiles

// ---------------- scratch (static device globals; no allocation) ----------------
__device__ __align__(16) float g_w1[D_IN];
__device__ __align__(16) float g_w2[D_IN];
__device__ __align__(16) float g_w1p[8][D_IN];
__device__ __align__(16) float g_w2p[8][D_IN];
__device__ float g_s_src[N_S];
__device__ float g_s_dst[N_P];
__device__ float g_inv[N_P];
__device__ int   g_cnt[N_P];
__device__ int   g_off[N_P + 1];
__device__ int   g_cur[N_P];
__device__ int   g_src_csr[EN];
__device__ float g_alpha[EN];
// fp16 copy of h_s: 51 MB gather table (written by k_scores, fused)
__device__ __align__(16) __half g_hs16[(size_t)N_S * D_IN];
// aggregated h per dst, single fp16 table (rows >= N_P stay zero)
__device__ __align__(16) __half g_agg16[(size_t)M_PAD * D_IN];
// W in fp16 hi/lo split (lo captures residual -> W near-exact across 2 MMAs)
__device__ __align__(16) __half g_Wh16[(size_t)D_OUT * D_IN];
__device__ __align__(16) __half g_Wl16[(size_t)D_OUT * D_IN];

__device__ __forceinline__ unsigned h2_bits(__half2 h) {
    return *reinterpret_cast<unsigned*>(&h);
}

// ---------------- K0: zero per-dst edge counts ----------------
__global__ void k_zero_cnt() {
    int i = blockIdx.x * blockDim.x + threadIdx.x;
    if (i < N_P) g_cnt[i] = 0;
}

// ---------------- K1a: fold attention vector, phase 1 (partials) ----------------
__global__ void __launch_bounds__(64) k_fold_part(const float* __restrict__ W,
                                                  const float* __restrict__ aw) {
    int kb = blockIdx.x & 7;
    int db = blockIdx.x >> 3;
    int k  = kb * 64 + threadIdx.x;
    int d0 = db * 32;
    float a1 = 0.f, a2 = 0.f;
    #pragma unroll
    for (int i = 0; i < 32; i++) {
        int d = d0 + i;
        float w = __ldg(&W[d * D_IN + k]);   // coalesced across the 64 threads
        a1 += w * __ldg(&aw[d]);
        a2 += w * __ldg(&aw[D_OUT + d]);
    }
    g_w1p[db][k] = a1;
    g_w2p[db][k] = a2;
}

// ---------------- K1a': fold phase 2 (reduce 8 partials) ----------------
__global__ void k_fold_red() {
    int k = threadIdx.x;   // 512 threads
    float a1 = 0.f, a2 = 0.f;
    #pragma unroll
    for (int i = 0; i < 8; i++) {
        a1 += g_w1p[i][k];
        a2 += g_w2p[i][k];
    }
    g_w1[k] = a1;
    g_w2[k] = a2;
}

// ---------------- K1b: split W into fp16 hi/lo ----------------
__global__ void k_convw(const float* __restrict__ W) {
    int i = blockIdx.x * blockDim.x + threadIdx.x;
    float v = W[i];
    __half hi = __float2half_rn(v);
    float r = v - __half2float(hi);
    g_Wh16[i] = hi;
    g_Wl16[i] = __float2half_rn(r);
}

// ---------------- K2: per-node scores + fused fp16 table emission ----------------
__global__ void k_scores(const float* __restrict__ hs, const float* __restrict__ hp) {
    int gw   = (blockIdx.x * blockDim.x + threadIdx.x) >> 5;
    int lane = threadIdx.x & 31;
    if (gw >= N_S + N_P) return;
    float acc = 0.f;
    if (gw < N_S) {
        const float4* row = (const float4*)(hs + (size_t)gw * D_IN);
        const float4* wv  = (const float4*)g_w1;
        __half* hrow = g_hs16 + (size_t)gw * D_IN;
        #pragma unroll
        for (int i = lane; i < D_IN / 4; i += 32) {
            float4 a = __ldg(row + i);
            float4 b = wv[i];
            acc += a.x * b.x + a.y * b.y + a.z * b.z + a.w * b.w;
            uint2 o;
            o.x = h2_bits(__floats2half2_rn(a.x, a.y));
            o.y = h2_bits(__floats2half2_rn(a.z, a.w));
            *reinterpret_cast<uint2*>(hrow + i * 4) = o;
        }
    } else {
        const float4* row = (const float4*)(hp + (size_t)(gw - N_S) * D_IN);
        const float4* wv  = (const float4*)g_w2;
        #pragma unroll
        for (int i = lane; i < D_IN / 4; i += 32) {
            float4 a = __ldcs(row + i);     // streaming: h_p never reused
            float4 b = wv[i];
            acc += a.x * b.x + a.y * b.y + a.z * b.z + a.w * b.w;
        }
    }
    #pragma unroll
    for (int o = 16; o; o >>= 1) acc += __shfl_xor_sync(0xffffffffu, acc, o);
    if (lane == 0) {
        if (gw < N_S) g_s_src[gw] = acc;
        else          g_s_dst[gw - N_S] = acc;
    }
}

// ---------------- K3: dst histogram (4 edges per thread) ----------------
__global__ void k_count(const int4* __restrict__ dst4) {
    int i = blockIdx.x * blockDim.x + threadIdx.x;
    if (i >= EN / 4) return;
    int4 d = dst4[i];
    atomicAdd(&g_cnt[d.x], 1);
    atomicAdd(&g_cnt[d.y], 1);
    atomicAdd(&g_cnt[d.z], 1);
    atomicAdd(&g_cnt[d.w], 1);
}

// ---------------- K4: exclusive scan of counts -> CSR offsets ----------------
__global__ void k_scan() {
    __shared__ int wsum[32];
    int t    = threadIdx.x;
    int lane = t & 31;
    int wid  = t >> 5;
    int base = t * 10;
    int incl_loc[10];
    int cnts[10];
    int tot = 0;
    if (t < 1000) {
        #pragma unroll
        for (int i = 0; i < 10; i++) {
            int c = g_cnt[base + i];
            cnts[i] = c;
            tot += c;
            incl_loc[i] = tot;
        }
    }
    int incl = tot;
    #pragma unroll
    for (int o = 1; o < 32; o <<= 1) {
        int v = __shfl_up_sync(0xffffffffu, incl, o);
        if (lane >= o) incl += v;
    }
    if (lane == 31) wsum[wid] = incl;
    __syncthreads();
    if (wid == 0) {
        int v = wsum[lane];
        #pragma unroll
        for (int o = 1; o < 32; o <<= 1) {
            int u = __shfl_up_sync(0xffffffffu, v, o);
            if (lane >= o) v += u;
        }
        wsum[lane] = v;
    }
    __syncthreads();
    int warpoff = (wid == 0) ? 0 : wsum[wid - 1];
    int texcl   = warpoff + incl - tot;
    if (t < 1000) {
        #pragma unroll
        for (int i = 0; i < 10; i++) {
            int iv = texcl + incl_loc[i];
            g_off[base + i + 1] = iv;
            g_cur[base + i]     = iv - cnts[i];
        }
    }
    if (t == 0) g_off[0] = 0;
}

// ---------------- K5: scatter src ids into CSR order (4 edges per thread) -------
__global__ void k_scatter(const int4* __restrict__ src4, const int4* __restrict__ dst4) {
    int i = blockIdx.x * blockDim.x + threadIdx.x;
    if (i >= EN / 4) return;
    int4 s = src4[i];
    int4 d = dst4[i];
    int p0 = atomicAdd(&g_cur[d.x], 1); g_src_csr[p0] = s.x;
    int p1 = atomicAdd(&g_cur[d.y], 1); g_src_csr[p1] = s.y;
    int p2 = atomicAdd(&g_cur[d.z], 1); g_src_csr[p2] = s.z;
    int p3 = atomicAdd(&g_cur[d.w], 1); g_src_csr[p3] = s.w;
}

// ---------------- K6: warp-per-dst softmax -> unnormalized ex + g_inv ----------
__global__ void k_softmax() {
    int p    = (blockIdx.x * blockDim.x + threadIdx.x) >> 5;
    int lane = threadIdx.x & 31;
    if (p >= N_P) return;
    int start = g_off[p];
    int cnt   = g_off[p + 1] - start;
    float sd  = g_s_dst[p];

    float m = -CUDART_INF_F;
    for (int j = lane; j < cnt; j += 32) {
        float v = g_s_src[g_src_csr[start + j]] + sd;
        v = (v > 0.f) ? v : 0.01f * v;
        m = fmaxf(m, v);
    }
    #pragma unroll
    for (int o = 16; o; o >>= 1) m = fmaxf(m, __shfl_xor_sync(0xffffffffu, m, o));

    float s = 0.f;
    for (int j = lane; j < cnt; j += 32) {
        float v = g_s_src[g_src_csr[start + j]] + sd;
        v = (v > 0.f) ? v : 0.01f * v;
        float ex = __expf(v - m);
        g_alpha[start + j] = ex;     // unnormalized (max-subtracted)
        s += ex;
    }
    #pragma unroll
    for (int o = 16; o; o >>= 1) s += __shfl_xor_sync(0xffffffffu, s, o);
    if (lane == 0) g_inv[p] = (cnt > 0) ? (1.0f / s) : 0.f;
}

// ---------------- K7: per-dst weighted gather-accumulate (R9-proven shape) ------
// 64 threads/block, block per dst; thread covers 8 cols (uint4 = 8 halves).
// Output: single fp16 row (one 16B streaming store).
__global__ void __launch_bounds__(64) k_aggregate(int pBase) {
    int p = pBase + blockIdx.x;
    int t = threadIdx.x;                       // 0..63
    int start = g_off[p];
    int cnt   = g_off[p + 1] - start;
    float inv = g_inv[p];

    __shared__ int   ss[64];
    __shared__ float ws[64];

    float acc[8] = {0.f, 0.f, 0.f, 0.f, 0.f, 0.f, 0.f, 0.f};
    for (int base = 0; base < cnt; base += 64) {
        int j = base + t;
        if (j < cnt) {
            ss[t] = g_src_csr[start + j];      // coalesced
            ws[t] = g_alpha[start + j];        // coalesced
        }
        __syncthreads();
        int lim = min(64, cnt - base);
        #pragma unroll 8
        for (int q = 0; q < lim; q++) {
            float w = ws[q];
            const uint4* row = (const uint4*)(g_hs16 + (size_t)ss[q] * D_IN) + t;
            uint4 u = __ldg(row);              // 8 halves
            float2 f0 = __half22float2(*reinterpret_cast<__half2*>(&u.x));
            float2 f1 = __half22float2(*reinterpret_cast<__half2*>(&u.y));
            float2 f2 = __half22float2(*reinterpret_cast<__half2*>(&u.z));
            float2 f3 = __half22float2(*reinterpret_cast<__half2*>(&u.w));
            acc[0] += w * f0.x;  acc[1] += w * f0.y;
            acc[2] += w * f1.x;  acc[3] += w * f1.y;
            acc[4] += w * f2.x;  acc[5] += w * f2.y;
            acc[6] += w * f3.x;  acc[7] += w * f3.y;
        }
        __syncthreads();
    }

    // normalize + pack 8 fp16, one streaming store
    uint4 o;
    o.x = h2_bits(__floats2half2_rn(acc[0] * inv, acc[1] * inv));
    o.y = h2_bits(__floats2half2_rn(acc[2] * inv, acc[3] * inv));
    o.z = h2_bits(__floats2half2_rn(acc[4] * inv, acc[5] * inv));
    o.w = h2_bits(__floats2half2_rn(acc[6] * inv, acc[7] * inv));
    asm volatile("st.global.cs.v4.u32 [%0], {%1,%2,%3,%4};"
                 :: "l"(g_agg16 + (size_t)p * D_IN + t * 8),
                    "r"(o.x), "r"(o.y), "r"(o.z), "r"(o.w));
}

// ---------------- K8: out = agg @ W^T via fp16 MMA (A single, W hi/lo) ----------
#define SMS 24   // smem row stride in halves (48B: 16B-aligned, conflict-free)

__device__ __forceinline__ void mma_f16(float d[4],
                                        unsigned a0, unsigned a1, unsigned a2, unsigned a3,
                                        unsigned b0, unsigned b1) {
    asm volatile(
        "mma.sync.aligned.m16n8k16.row.col.f32.f16.f16.f32 "
        "{%0,%1,%2,%3}, {%4,%5,%6,%7}, {%8,%9}, {%0,%1,%2,%3};\n"
        : "+f"(d[0]), "+f"(d[1]), "+f"(d[2]), "+f"(d[3])
        : "r"(a0), "r"(a1), "r"(a2), "r"(a3), "r"(b0), "r"(b1));
}

__device__ __forceinline__ void ldsm4(unsigned& r0, unsigned& r1, unsigned& r2, unsigned& r3,
                                      unsigned addr) {
    asm volatile("ldmatrix.sync.aligned.m8n8.x4.shared.b16 {%0,%1,%2,%3}, [%4];"
                 : "=r"(r0), "=r"(r1), "=r"(r2), "=r"(r3) : "r"(addr));
}

__global__ void __launch_bounds__(256) k_gemm_mma(float* __restrict__ out, int bmBase) {
    __shared__ __align__(16) __half sA[128 * SMS];
    __shared__ __align__(16) __half sBh[128 * SMS];
    __shared__ __align__(16) __half sBl[128 * SMS];

    const int bm = (blockIdx.x + bmBase) * 128;
    const int bn = blockIdx.y * 128;
    const int tid  = threadIdx.x;
    const int lane = tid & 31;
    const int warp = tid >> 5;
    const int wm = (warp >> 1) * 32;
    const int wn = (warp & 1) * 64;
    const int g  = lane >> 2;
    const int tg = lane & 3;

    const int lrow = tid >> 1;
    const int lc8  = (tid & 1) * 8;

    const __half* gA  = g_agg16 + (size_t)(bm + lrow) * D_IN + lc8;
    const __half* gBh = g_Wh16  + (size_t)(bn + lrow) * D_IN + lc8;
    const __half* gBl = g_Wl16  + (size_t)(bn + lrow) * D_IN + lc8;

    float d[2][8][4];
    #pragma unroll
    for (int mt = 0; mt < 2; mt++)
        #pragma unroll
        for (int nt = 0; nt < 8; nt++)
            #pragma unroll
            for (int i = 0; i < 4; i++) d[mt][nt][i] = 0.f;

    uint4 ra  = *(const uint4*)gA;
    uint4 rbh = *(const uint4*)gBh;
    uint4 rbl = *(const uint4*)gBl;

    const int sidx = lrow * SMS + lc8;

    const unsigned baseA  = (unsigned)__cvta_generic_to_shared(sA);
    const unsigned baseBh = (unsigned)__cvta_generic_to_shared(sBh);
    const unsigned baseBl = (unsigned)__cvta_generic_to_shared(sBl);

    const int arow = (lane & 15);
    const int akb  = (lane >> 4) * 16;
    unsigned aAddr[2];
    #pragma unroll
    for (int mt = 0; mt < 2; mt++) {
        int r = wm + mt * 16 + arow;
        aAddr[mt] = baseA + r * (SMS * 2) + akb;
    }
    const int brow = (lane & 7) + ((lane >> 4) & 1) * 8;
    const int bkb  = ((lane >> 3) & 1) * 16;
    unsigned bAddr[4], bAddrL[4];
    #pragma unroll
    for (int ntp = 0; ntp < 4; ntp++) {
        int r = wn + ntp * 16 + brow;
        bAddr[ntp]  = baseBh + r * (SMS * 2) + bkb;
        bAddrL[ntp] = baseBl + r * (SMS * 2) + bkb;
    }

    for (int ks = 0; ks < D_IN / 16; ks++) {
        *(uint4*)(sA + sidx)  = ra;
        *(uint4*)(sBh + sidx) = rbh;
        *(uint4*)(sBl + sidx) = rbl;
        __syncthreads();

        if (ks < D_IN / 16 - 1) {
            int koff = (ks + 1) * 16;
            ra  = *(const uint4*)(gA + koff);
            rbh = *(const uint4*)(gBh + koff);
            rbl = *(const uint4*)(gBl + koff);
        }

        unsigned ah[2][4];
        #pragma unroll
        for (int mt = 0; mt < 2; mt++)
            ldsm4(ah[mt][0], ah[mt][1], ah[mt][2], ah[mt][3], aAddr[mt]);
        unsigned bh[4][4], bl[4][4];
        #pragma unroll
        for (int ntp = 0; ntp < 4; ntp++) {
            ldsm4(bh[ntp][0], bh[ntp][1], bh[ntp][2], bh[ntp][3], bAddr[ntp]);
            ldsm4(bl[ntp][0], bl[ntp][1], bl[ntp][2], bl[ntp][3], bAddrL[ntp]);
        }

        #pragma unroll
        for (int nt = 0; nt < 8; nt++) {
            int ntp = nt >> 1;
            int o   = (nt & 1) * 2;
            unsigned bh0 = bh[ntp][o], bh1 = bh[ntp][o + 1];
            unsigned bl0 = bl[ntp][o], bl1 = bl[ntp][o + 1];
            #pragma unroll
            for (int mt = 0; mt < 2; mt++) {
                mma_f16(d[mt][nt], ah[mt][0], ah[mt][1], ah[mt][2], ah[mt][3], bh0, bh1);
                mma_f16(d[mt][nt], ah[mt][0], ah[mt][1], ah[mt][2], ah[mt][3], bl0, bl1);
            }
        }
        __syncthreads();
    }

    #pragma unroll
    for (int mt = 0; mt < 2; mt++) {
        #pragma unroll
        for (int nt = 0; nt < 8; nt++) {
            int r0 = bm + wm + mt * 16 + g;
            int c  = bn + wn + nt * 8 + tg * 2;
            if (r0 < N_P) {
                float2 v0 = make_float2(d[mt][nt][0], d[mt][nt][1]);
                *(float2*)(out + (size_t)r0 * D_OUT + c) = v0;
            }
            if (r0 + 8 < N_P) {
                float2 v1 = make_float2(d[mt][nt][2], d[mt][nt][3]);
                *(float2*)(out + (size_t)(r0 + 8) * D_OUT + c) = v1;
            }
        }
    }
}

// ---------------- stream/event context (created at load, before harness checkpoints)
struct HxCtx {
    cudaStream_t sB, sC;
    cudaEvent_t evRoot, evB, evG1, evG2, evC;
    HxCtx() {
        cudaStreamCreateWithFlags(&sB, cudaStreamNonBlocking);
        cudaStreamCreateWithFlags(&sC, cudaStreamNonBlocking);
        cudaEventCreateWithFlags(&evRoot, cudaEventDisableTiming);
        cudaEventCreateWithFlags(&evB,    cudaEventDisableTiming);
        cudaEventCreateWithFlags(&evG1,   cudaEventDisableTiming);
        cudaEventCreateWithFlags(&evG2,   cudaEventDisableTiming);
        cudaEventCreateWithFlags(&evC,    cudaEventDisableTiming);
    }
};
static HxCtx hx;

// ---------------- launch ----------------
extern "C" void kernel_launch(void* const* d_in, const int* in_sizes, int n_in,
                              void* d_out, int out_size) {
    const float* hs  = (const float*)d_in[0];
    const float* hp  = (const float*)d_in[1];
    const float* W   = (const float*)d_in[2];
    const float* aw  = (const float*)d_in[3];
    const int*   src = (const int*)d_in[4];
    const int*   dst = (const int*)d_in[5];
    float*       out = (float*)d_out;

    // fork
    cudaEventRecord(hx.evRoot, 0);
    cudaStreamWaitEvent(hx.sB, hx.evRoot, 0);
    cudaStreamWaitEvent(hx.sC, hx.evRoot, 0);

    // chain B (edge structure): zero -> count -> scan -> scatter
    k_zero_cnt<<<(N_P + 255) / 256, 256, 0, hx.sB>>>();
    k_count<<<(EN / 4 + 255) / 256, 256, 0, hx.sB>>>((const int4*)dst);
    k_scan<<<1, 1024, 0, hx.sB>>>();
    k_scatter<<<(EN / 4 + 255) / 256, 256, 0, hx.sB>>>((const int4*)src, (const int4*)dst);
    cudaEventRecord(hx.evB, hx.sB);

    // chain C (weights): convw, later gemm
    k_convw<<<(D_OUT * D_IN) / 1024, 1024, 0, hx.sC>>>(W);

    // chain 0: fold (2-phase) -> scores(+fp16 table) -> join B -> softmax -> aggregate
    k_fold_part<<<64, 64>>>(W, aw);
    k_fold_red<<<1, 512>>>();
    k_scores<<<((N_S + N_P) * 32 + 255) / 256, 256>>>(hs, hp);
    cudaStreamWaitEvent(0, hx.evB, 0);
    k_softmax<<<(N_P * 32 + 255) / 256, 256>>>();
    k_aggregate<<<ROW_SPLIT, 64>>>(0);
    cudaEventRecord(hx.evG1, 0);
    k_aggregate<<<N_P - ROW_SPLIT, 64>>>(ROW_SPLIT);
    cudaEventRecord(hx.evG2, 0);

    // gemm pipelined on chain C (overlaps second aggregate half)
    cudaStreamWaitEvent(hx.sC, hx.evG1, 0);
    k_gemm_mma<<<dim3(ROW_SPLIT / 128, D_OUT / 128), 256, 0, hx.sC>>>(out, 0);
    cudaStreamWaitEvent(hx.sC, hx.evG2, 0);
    k_gemm_mma<<<dim3(M_PAD / 128 - ROW_SPLIT / 128, D_OUT / 128), 256, 0, hx.sC>>>(out, ROW_SPLIT / 128);
    cudaEventRecord(hx.evC, hx.sC);

    // join everything back to the capture stream
    cudaStreamWaitEvent(0, hx.evC, 0);
}

// round 17
// speedup vs baseline: 1.3390x; 1.0716x over previous
#include <cuda_runtime.h>
#include <cuda_fp16.h>
#include <math_constants.h>

#define N_S   50000
#define N_P   10000
#define EN    320000
#define D_IN  512
#define D_OUT 256
#define M_PAD 10112   // 79 * 128
#define ROW_SPLIT 5120  // 40 gemm M-tiles

// ---------------- scratch (static device globals; no allocation) ----------------
__device__ __align__(16) float g_w1[D_IN];
__device__ __align__(16) float g_w2[D_IN];
__device__ __align__(16) float g_w1p[8][D_IN];
__device__ __align__(16) float g_w2p[8][D_IN];
__device__ float g_s_src[N_S];
__device__ float g_s_dst[N_P];
__device__ float g_inv[N_P];
__device__ int   g_cnt[N_P];
__device__ int   g_off[N_P + 1];
__device__ int   g_cur[N_P];
__device__ int   g_src_csr[EN];
__device__ float g_alpha[EN];
// fp16 copy of h_s: 51 MB gather table (written by k_scores, fused)
__device__ __align__(16) __half g_hs16[(size_t)N_S * D_IN];
// aggregated h per dst, single fp16 table (rows >= N_P stay zero)
__device__ __align__(16) __half g_agg16[(size_t)M_PAD * D_IN];
// W in fp16 (single precision level; RMS error budget allows it)
__device__ __align__(16) __half g_Wh16[(size_t)D_OUT * D_IN];

__device__ __forceinline__ unsigned h2_bits(__half2 h) {
    return *reinterpret_cast<unsigned*>(&h);
}

// ---------------- K0: zero per-dst edge counts ----------------
__global__ void k_zero_cnt() {
    int i = blockIdx.x * blockDim.x + threadIdx.x;
    if (i < N_P) g_cnt[i] = 0;
}

// ---------------- K1a: fold attention vector, phase 1 (partials) ----------------
__global__ void __launch_bounds__(64) k_fold_part(const float* __restrict__ W,
                                                  const float* __restrict__ aw) {
    int kb = blockIdx.x & 7;
    int db = blockIdx.x >> 3;
    int k  = kb * 64 + threadIdx.x;
    int d0 = db * 32;
    float a1 = 0.f, a2 = 0.f;
    #pragma unroll
    for (int i = 0; i < 32; i++) {
        int d = d0 + i;
        float w = __ldg(&W[d * D_IN + k]);   // coalesced across the 64 threads
        a1 += w * __ldg(&aw[d]);
        a2 += w * __ldg(&aw[D_OUT + d]);
    }
    g_w1p[db][k] = a1;
    g_w2p[db][k] = a2;
}

// ---------------- K1a': fold phase 2 (reduce 8 partials) ----------------
__global__ void k_fold_red() {
    int k = threadIdx.x;   // 512 threads
    float a1 = 0.f, a2 = 0.f;
    #pragma unroll
    for (int i = 0; i < 8; i++) {
        a1 += g_w1p[i][k];
        a2 += g_w2p[i][k];
    }
    g_w1[k] = a1;
    g_w2[k] = a2;
}

// ---------------- K1b: convert W to fp16 ----------------
__global__ void k_convw(const float* __restrict__ W) {
    int i = blockIdx.x * blockDim.x + threadIdx.x;
    g_Wh16[i] = __float2half_rn(W[i]);
}

// ---------------- K2: per-node scores + fused fp16 table emission ----------------
__global__ void k_scores(const float* __restrict__ hs, const float* __restrict__ hp) {
    int gw   = (blockIdx.x * blockDim.x + threadIdx.x) >> 5;
    int lane = threadIdx.x & 31;
    if (gw >= N_S + N_P) return;
    float acc = 0.f;
    if (gw < N_S) {
        const float4* row = (const float4*)(hs + (size_t)gw * D_IN);
        const float4* wv  = (const float4*)g_w1;
        __half* hrow = g_hs16 + (size_t)gw * D_IN;
        #pragma unroll
        for (int i = lane; i < D_IN / 4; i += 32) {
            float4 a = __ldg(row + i);
            float4 b = wv[i];
            acc += a.x * b.x + a.y * b.y + a.z * b.z + a.w * b.w;
            uint2 o;
            o.x = h2_bits(__floats2half2_rn(a.x, a.y));
            o.y = h2_bits(__floats2half2_rn(a.z, a.w));
            *reinterpret_cast<uint2*>(hrow + i * 4) = o;
        }
    } else {
        const float4* row = (const float4*)(hp + (size_t)(gw - N_S) * D_IN);
        const float4* wv  = (const float4*)g_w2;
        #pragma unroll
        for (int i = lane; i < D_IN / 4; i += 32) {
            float4 a = __ldcs(row + i);     // streaming: h_p never reused
            float4 b = wv[i];
            acc += a.x * b.x + a.y * b.y + a.z * b.z + a.w * b.w;
        }
    }
    #pragma unroll
    for (int o = 16; o; o >>= 1) acc += __shfl_xor_sync(0xffffffffu, acc, o);
    if (lane == 0) {
        if (gw < N_S) g_s_src[gw] = acc;
        else          g_s_dst[gw - N_S] = acc;
    }
}

// ---------------- K3: dst histogram (4 edges per thread) ----------------
__global__ void k_count(const int4* __restrict__ dst4) {
    int i = blockIdx.x * blockDim.x + threadIdx.x;
    if (i >= EN / 4) return;
    int4 d = dst4[i];
    atomicAdd(&g_cnt[d.x], 1);
    atomicAdd(&g_cnt[d.y], 1);
    atomicAdd(&g_cnt[d.z], 1);
    atomicAdd(&g_cnt[d.w], 1);
}

// ---------------- K4: exclusive scan of counts -> CSR offsets ----------------
__global__ void k_scan() {
    __shared__ int wsum[32];
    int t    = threadIdx.x;
    int lane = t & 31;
    int wid  = t >> 5;
    int base = t * 10;
    int incl_loc[10];
    int cnts[10];
    int tot = 0;
    if (t < 1000) {
        #pragma unroll
        for (int i = 0; i < 10; i++) {
            int c = g_cnt[base + i];
            cnts[i] = c;
            tot += c;
            incl_loc[i] = tot;
        }
    }
    int incl = tot;
    #pragma unroll
    for (int o = 1; o < 32; o <<= 1) {
        int v = __shfl_up_sync(0xffffffffu, incl, o);
        if (lane >= o) incl += v;
    }
    if (lane == 31) wsum[wid] = incl;
    __syncthreads();
    if (wid == 0) {
        int v = wsum[lane];
        #pragma unroll
        for (int o = 1; o < 32; o <<= 1) {
            int u = __shfl_up_sync(0xffffffffu, v, o);
            if (lane >= o) v += u;
        }
        wsum[lane] = v;
    }
    __syncthreads();
    int warpoff = (wid == 0) ? 0 : wsum[wid - 1];
    int texcl   = warpoff + incl - tot;
    if (t < 1000) {
        #pragma unroll
        for (int i = 0; i < 10; i++) {
            int iv = texcl + incl_loc[i];
            g_off[base + i + 1] = iv;
            g_cur[base + i]     = iv - cnts[i];
        }
    }
    if (t == 0) g_off[0] = 0;
}

// ---------------- K5: scatter src ids into CSR order (4 edges per thread) -------
__global__ void k_scatter(const int4* __restrict__ src4, const int4* __restrict__ dst4) {
    int i = blockIdx.x * blockDim.x + threadIdx.x;
    if (i >= EN / 4) return;
    int4 s = src4[i];
    int4 d = dst4[i];
    int p0 = atomicAdd(&g_cur[d.x], 1); g_src_csr[p0] = s.x;
    int p1 = atomicAdd(&g_cur[d.y], 1); g_src_csr[p1] = s.y;
    int p2 = atomicAdd(&g_cur[d.z], 1); g_src_csr[p2] = s.z;
    int p3 = atomicAdd(&g_cur[d.w], 1); g_src_csr[p3] = s.w;
}

// ---------------- K6: warp-per-dst softmax -> unnormalized ex + g_inv ----------
__global__ void k_softmax() {
    int p    = (blockIdx.x * blockDim.x + threadIdx.x) >> 5;
    int lane = threadIdx.x & 31;
    if (p >= N_P) return;
    int start = g_off[p];
    int cnt   = g_off[p + 1] - start;
    float sd  = g_s_dst[p];

    float m = -CUDART_INF_F;
    for (int j = lane; j < cnt; j += 32) {
        float v = g_s_src[g_src_csr[start + j]] + sd;
        v = (v > 0.f) ? v : 0.01f * v;
        m = fmaxf(m, v);
    }
    #pragma unroll
    for (int o = 16; o; o >>= 1) m = fmaxf(m, __shfl_xor_sync(0xffffffffu, m, o));

    float s = 0.f;
    for (int j = lane; j < cnt; j += 32) {
        float v = g_s_src[g_src_csr[start + j]] + sd;
        v = (v > 0.f) ? v : 0.01f * v;
        float ex = __expf(v - m);
        g_alpha[start + j] = ex;     // unnormalized (max-subtracted)
        s += ex;
    }
    #pragma unroll
    for (int o = 16; o; o >>= 1) s += __shfl_xor_sync(0xffffffffu, s, o);
    if (lane == 0) g_inv[p] = (cnt > 0) ? (1.0f / s) : 0.f;
}

// ---------------- K7: per-dst weighted gather-accumulate (R9-proven shape) ------
// 64 threads/block, block per dst; thread covers 8 cols (uint4 = 8 halves).
__global__ void __launch_bounds__(64) k_aggregate(int pBase) {
    int p = pBase + blockIdx.x;
    int t = threadIdx.x;                       // 0..63
    int start = g_off[p];
    int cnt   = g_off[p + 1] - start;
    float inv = g_inv[p];

    __shared__ int   ss[64];
    __shared__ float ws[64];

    float acc[8] = {0.f, 0.f, 0.f, 0.f, 0.f, 0.f, 0.f, 0.f};
    for (int base = 0; base < cnt; base += 64) {
        int j = base + t;
        if (j < cnt) {
            ss[t] = g_src_csr[start + j];      // coalesced
            ws[t] = g_alpha[start + j];        // coalesced
        }
        __syncthreads();
        int lim = min(64, cnt - base);
        #pragma unroll 8
        for (int q = 0; q < lim; q++) {
            float w = ws[q];
            const uint4* row = (const uint4*)(g_hs16 + (size_t)ss[q] * D_IN) + t;
            uint4 u = __ldg(row);              // 8 halves
            float2 f0 = __half22float2(*reinterpret_cast<__half2*>(&u.x));
            float2 f1 = __half22float2(*reinterpret_cast<__half2*>(&u.y));
            float2 f2 = __half22float2(*reinterpret_cast<__half2*>(&u.z));
            float2 f3 = __half22float2(*reinterpret_cast<__half2*>(&u.w));
            acc[0] += w * f0.x;  acc[1] += w * f0.y;
            acc[2] += w * f1.x;  acc[3] += w * f1.y;
            acc[4] += w * f2.x;  acc[5] += w * f2.y;
            acc[6] += w * f3.x;  acc[7] += w * f3.y;
        }
        __syncthreads();
    }

    // normalize + pack 8 fp16, one streaming store
    uint4 o;
    o.x = h2_bits(__floats2half2_rn(acc[0] * inv, acc[1] * inv));
    o.y = h2_bits(__floats2half2_rn(acc[2] * inv, acc[3] * inv));
    o.z = h2_bits(__floats2half2_rn(acc[4] * inv, acc[5] * inv));
    o.w = h2_bits(__floats2half2_rn(acc[6] * inv, acc[7] * inv));
    asm volatile("st.global.cs.v4.u32 [%0], {%1,%2,%3,%4};"
                 :: "l"(g_agg16 + (size_t)p * D_IN + t * 8),
                    "r"(o.x), "r"(o.y), "r"(o.z), "r"(o.w));
}

// ---------------- K8: out = agg @ W^T via single fp16 MMA ----------------
#define SMS 24   // smem row stride in halves (48B: 16B-aligned, conflict-free)

__device__ __forceinline__ void mma_f16(float d[4],
                                        unsigned a0, unsigned a1, unsigned a2, unsigned a3,
                                        unsigned b0, unsigned b1) {
    asm volatile(
        "mma.sync.aligned.m16n8k16.row.col.f32.f16.f16.f32 "
        "{%0,%1,%2,%3}, {%4,%5,%6,%7}, {%8,%9}, {%0,%1,%2,%3};\n"
        : "+f"(d[0]), "+f"(d[1]), "+f"(d[2]), "+f"(d[3])
        : "r"(a0), "r"(a1), "r"(a2), "r"(a3), "r"(b0), "r"(b1));
}

__device__ __forceinline__ void ldsm4(unsigned& r0, unsigned& r1, unsigned& r2, unsigned& r3,
                                      unsigned addr) {
    asm volatile("ldmatrix.sync.aligned.m8n8.x4.shared.b16 {%0,%1,%2,%3}, [%4];"
                 : "=r"(r0), "=r"(r1), "=r"(r2), "=r"(r3) : "r"(addr));
}

__global__ void __launch_bounds__(256) k_gemm_mma(float* __restrict__ out, int bmBase) {
    __shared__ __align__(16) __half sA[128 * SMS];
    __shared__ __align__(16) __half sB[128 * SMS];

    const int bm = (blockIdx.x + bmBase) * 128;
    const int bn = blockIdx.y * 128;
    const int tid  = threadIdx.x;
    const int lane = tid & 31;
    const int warp = tid >> 5;
    const int wm = (warp >> 1) * 32;
    const int wn = (warp & 1) * 64;
    const int g  = lane >> 2;
    const int tg = lane & 3;

    const int lrow = tid >> 1;
    const int lc8  = (tid & 1) * 8;

    const __half* gA = g_agg16 + (size_t)(bm + lrow) * D_IN + lc8;
    const __half* gB = g_Wh16  + (size_t)(bn + lrow) * D_IN + lc8;

    float d[2][8][4];
    #pragma unroll
    for (int mt = 0; mt < 2; mt++)
        #pragma unroll
        for (int nt = 0; nt < 8; nt++)
            #pragma unroll
            for (int i = 0; i < 4; i++) d[mt][nt][i] = 0.f;

    uint4 ra = *(const uint4*)gA;
    uint4 rb = *(const uint4*)gB;

    const int sidx = lrow * SMS + lc8;

    const unsigned baseA = (unsigned)__cvta_generic_to_shared(sA);
    const unsigned baseB = (unsigned)__cvta_generic_to_shared(sB);

    const int arow = (lane & 15);
    const int akb  = (lane >> 4) * 16;
    unsigned aAddr[2];
    #pragma unroll
    for (int mt = 0; mt < 2; mt++) {
        int r = wm + mt * 16 + arow;
        aAddr[mt] = baseA + r * (SMS * 2) + akb;
    }
    const int brow = (lane & 7) + ((lane >> 4) & 1) * 8;
    const int bkb  = ((lane >> 3) & 1) * 16;
    unsigned bAddr[4];
    #pragma unroll
    for (int ntp = 0; ntp < 4; ntp++) {
        int r = wn + ntp * 16 + brow;
        bAddr[ntp] = baseB + r * (SMS * 2) + bkb;
    }

    for (int ks = 0; ks < D_IN / 16; ks++) {
        *(uint4*)(sA + sidx) = ra;
        *(uint4*)(sB + sidx) = rb;
        __syncthreads();

        if (ks < D_IN / 16 - 1) {
            int koff = (ks + 1) * 16;
            ra = *(const uint4*)(gA + koff);
            rb = *(const uint4*)(gB + koff);
        }

        unsigned ah[2][4];
        #pragma unroll
        for (int mt = 0; mt < 2; mt++)
            ldsm4(ah[mt][0], ah[mt][1], ah[mt][2], ah[mt][3], aAddr[mt]);
        unsigned bh[4][4];
        #pragma unroll
        for (int ntp = 0; ntp < 4; ntp++)
            ldsm4(bh[ntp][0], bh[ntp][1], bh[ntp][2], bh[ntp][3], bAddr[ntp]);

        #pragma unroll
        for (int nt = 0; nt < 8; nt++) {
            int ntp = nt >> 1;
            int o   = (nt & 1) * 2;
            unsigned b0 = bh[ntp][o], b1 = bh[ntp][o + 1];
            #pragma unroll
            for (int mt = 0; mt < 2; mt++)
                mma_f16(d[mt][nt], ah[mt][0], ah[mt][1], ah[mt][2], ah[mt][3], b0, b1);
        }
        __syncthreads();
    }

    #pragma unroll
    for (int mt = 0; mt < 2; mt++) {
        #pragma unroll
        for (int nt = 0; nt < 8; nt++) {
            int r0 = bm + wm + mt * 16 + g;
            int c  = bn + wn + nt * 8 + tg * 2;
            if (r0 < N_P) {
                float2 v0 = make_float2(d[mt][nt][0], d[mt][nt][1]);
                *(float2*)(out + (size_t)r0 * D_OUT + c) = v0;
            }
            if (r0 + 8 < N_P) {
                float2 v1 = make_float2(d[mt][nt][2], d[mt][nt][3]);
                *(float2*)(out + (size_t)(r0 + 8) * D_OUT + c) = v1;
            }
        }
    }
}

// ---------------- stream/event context (created at load, before harness checkpoints)
struct HxCtx {
    cudaStream_t sB, sC;
    cudaEvent_t evRoot, evB, evG1, evG2, evC;
    HxCtx() {
        cudaStreamCreateWithFlags(&sB, cudaStreamNonBlocking);
        cudaStreamCreateWithFlags(&sC, cudaStreamNonBlocking);
        cudaEventCreateWithFlags(&evRoot, cudaEventDisableTiming);
        cudaEventCreateWithFlags(&evB,    cudaEventDisableTiming);
        cudaEventCreateWithFlags(&evG1,   cudaEventDisableTiming);
        cudaEventCreateWithFlags(&evG2,   cudaEventDisableTiming);
        cudaEventCreateWithFlags(&evC,    cudaEventDisableTiming);
    }
};
static HxCtx hx;

// ---------------- launch ----------------
extern "C" void kernel_launch(void* const* d_in, const int* in_sizes, int n_in,
                              void* d_out, int out_size) {
    const float* hs  = (const float*)d_in[0];
    const float* hp  = (const float*)d_in[1];
    const float* W   = (const float*)d_in[2];
    const float* aw  = (const float*)d_in[3];
    const int*   src = (const int*)d_in[4];
    const int*   dst = (const int*)d_in[5];
    float*       out = (float*)d_out;

    // fork
    cudaEventRecord(hx.evRoot, 0);
    cudaStreamWaitEvent(hx.sB, hx.evRoot, 0);
    cudaStreamWaitEvent(hx.sC, hx.evRoot, 0);

    // chain B (edge structure): zero -> count -> scan -> scatter
    k_zero_cnt<<<(N_P + 255) / 256, 256, 0, hx.sB>>>();
    k_count<<<(EN / 4 + 255) / 256, 256, 0, hx.sB>>>((const int4*)dst);
    k_scan<<<1, 1024, 0, hx.sB>>>();
    k_scatter<<<(EN / 4 + 255) / 256, 256, 0, hx.sB>>>((const int4*)src, (const int4*)dst);
    cudaEventRecord(hx.evB, hx.sB);

    // chain C (weights): convw, later gemm
    k_convw<<<(D_OUT * D_IN) / 1024, 1024, 0, hx.sC>>>(W);

    // chain 0: fold (2-phase) -> scores(+fp16 table) -> join B -> softmax -> aggregate
    k_fold_part<<<64, 64>>>(W, aw);
    k_fold_red<<<1, 512>>>();
    k_scores<<<((N_S + N_P) * 32 + 255) / 256, 256>>>(hs, hp);
    cudaStreamWaitEvent(0, hx.evB, 0);
    k_softmax<<<(N_P * 32 + 255) / 256, 256>>>();
    k_aggregate<<<ROW_SPLIT, 64>>>(0);
    cudaEventRecord(hx.evG1, 0);
    k_aggregate<<<N_P - ROW_SPLIT, 64>>>(ROW_SPLIT);
    cudaEventRecord(hx.evG2, 0);

    // gemm pipelined on chain C (overlaps second aggregate half)
    cudaStreamWaitEvent(hx.sC, hx.evG1, 0);
    k_gemm_mma<<<dim3(ROW_SPLIT / 128, D_OUT / 128), 256, 0, hx.sC>>>(out, 0);
    cudaStreamWaitEvent(hx.sC, hx.evG2, 0);
    k_gemm_mma<<<dim3(M_PAD / 128 - ROW_SPLIT / 128, D_OUT / 128), 256, 0, hx.sC>>>(out, ROW_SPLIT / 128);
    cudaEventRecord(hx.evC, hx.sC);

    // join everything back to the capture stream
    cudaStreamWaitEvent(0, hx.evC, 0);
}